// round 1
// baseline (speedup 1.0000x reference)
#include <cuda_runtime.h>
#include <math.h>
#include <float.h>

#define BB 256
#define TT 200
#define EE 100
#define EP 112          // E padded to multiple of 16
#define HH 512
#define G4 2048
#define NCLS 5
#define VV 50000
#define MROWS (TT*BB)   // 51200

// ---------------- static device scratch (no runtime allocation) ----------------
__device__ float g_xe[(size_t)MROWS * EP];     // gathered+padded embeddings
__device__ float g_W0p[(size_t)G4 * EP];       // W_ih0 padded to K=112
__device__ float g_G[(size_t)MROWS * G4];      // input-GEMM results (reused L0 then L1)
__device__ float g_h0s[(size_t)MROWS * HH];    // layer0 h archive (also A for G1 GEMM)
__device__ float g_h1[2 * BB * HH];            // layer1 h double buffer
__device__ float g_c[BB * HH];                 // cell state (per layer, re-inited)
__device__ float g_zero[BB * HH];              // h_{-1} = 0
__device__ float g_pooled[BB * HH];            // running max
__device__ int   g_last[BB];                   // last non-pad position per row

// ---------------- packed f32x2 helpers (128 FMA/cyc/SM path) ----------------
__device__ __forceinline__ unsigned long long pk2(float lo, float hi) {
    unsigned long long r;
    asm("mov.b64 %0, {%1,%2};" : "=l"(r) : "f"(lo), "f"(hi));
    return r;
}
__device__ __forceinline__ void upk2(float& lo, float& hi, unsigned long long v) {
    asm("mov.b64 {%0,%1}, %2;" : "=f"(lo), "=f"(hi) : "l"(v));
}
__device__ __forceinline__ void fma2(unsigned long long& d, unsigned long long a, unsigned long long b) {
    asm("fma.rn.f32x2 %0, %1, %2, %0;" : "+l"(d) : "l"(a), "l"(b));
}

__device__ __forceinline__ float sigf(float x) { return 1.0f / (1.0f + expf(-x)); }

// ---------------- small prep kernels ----------------
__global__ void k_last(const int* __restrict__ X) {
    int b = threadIdx.x;
    if (b < BB) {
        int l = -1;
        for (int t = 0; t < TT; t++)
            if (X[b * TT + t] != VV) l = t;
        g_last[b] = l;
    }
}

__global__ void k_padw0(const float* __restrict__ W) {
    int idx = blockIdx.x * blockDim.x + threadIdx.x;
    if (idx < G4 * EP) {
        int n = idx / EP, k = idx % EP;
        g_W0p[idx] = (k < EE) ? W[n * EE + k] : 0.0f;
    }
}

__global__ void k_gather(const int* __restrict__ X, const float* __restrict__ emb) {
    int row = blockIdx.x;              // row = t*BB + b
    int t = row / BB, b = row % BB;
    int tok = X[b * TT + t];
    const float* src = emb + (size_t)tok * EE;
    for (int e = threadIdx.x; e < EP; e += blockDim.x)
        g_xe[(size_t)row * EP + e] = (e < EE) ? src[e] : 0.0f;
}

__global__ void k_init(int layer) {
    int i = blockIdx.x * blockDim.x + threadIdx.x;
    if (i < BB * HH) {
        g_c[i] = 0.0f;
        if (layer == 0) g_zero[i] = 0.0f;
        else            g_pooled[i] = -FLT_MAX;
    }
}

// ---------------- big input GEMM: C[M,4H] = A[M,K] @ W[4H,K]^T + bias ----------------
// 128x128 tile, 256 threads, 8x8 microtile via packed f32x2 FMAs.
__global__ void __launch_bounds__(256) k_gemm(const float* __restrict__ Wihp,
                                              const float* __restrict__ bias,
                                              int which) {
    const float* A; const float* W; int K;
    if (which == 0) { A = g_xe;  W = g_W0p; K = EP; }
    else            { A = g_h0s; W = Wihp;  K = HH; }
    float* C = g_G;

    __shared__ float As[16][132];   // [k][m], row = 528B (16B aligned)
    __shared__ float Bs[16][132];   // [k][n]

    int m0 = blockIdx.y * 128, n0 = blockIdx.x * 128;
    int tx = threadIdx.x;
    int tn = tx & 15, tm = tx >> 4;

    unsigned long long acc[8][4];
#pragma unroll
    for (int i = 0; i < 8; i++)
#pragma unroll
        for (int j = 0; j < 4; j++) acc[i][j] = 0ull;

    for (int k0 = 0; k0 < K; k0 += 16) {
#pragma unroll
        for (int i = 0; i < 2; i++) {
            int id = i * 256 + tx;
            int row = id >> 2;
            int kq = (id & 3) * 4;
            float4 va = *(const float4*)(A + (size_t)(m0 + row) * K + k0 + kq);
            As[kq + 0][row] = va.x; As[kq + 1][row] = va.y;
            As[kq + 2][row] = va.z; As[kq + 3][row] = va.w;
            float4 vb = *(const float4*)(W + (size_t)(n0 + row) * K + k0 + kq);
            Bs[kq + 0][row] = vb.x; Bs[kq + 1][row] = vb.y;
            Bs[kq + 2][row] = vb.z; Bs[kq + 3][row] = vb.w;
        }
        __syncthreads();
#pragma unroll
        for (int k = 0; k < 16; k++) {
            float4 a0 = *(const float4*)&As[k][tm * 4];
            float4 a1 = *(const float4*)&As[k][64 + tm * 4];
            float4 b0 = *(const float4*)&Bs[k][tn * 4];
            float4 b1 = *(const float4*)&Bs[k][64 + tn * 4];
            unsigned long long pb[4] = { pk2(b0.x, b0.y), pk2(b0.z, b0.w),
                                         pk2(b1.x, b1.y), pk2(b1.z, b1.w) };
            float am[8] = { a0.x, a0.y, a0.z, a0.w, a1.x, a1.y, a1.z, a1.w };
#pragma unroll
            for (int mi = 0; mi < 8; mi++) {
                unsigned long long pa = pk2(am[mi], am[mi]);
#pragma unroll
                for (int np = 0; np < 4; np++) fma2(acc[mi][np], pa, pb[np]);
            }
        }
        __syncthreads();
    }

    float4 bi0 = *(const float4*)(bias + n0 + tn * 4);
    float4 bi1 = *(const float4*)(bias + n0 + 64 + tn * 4);
#pragma unroll
    for (int mi = 0; mi < 8; mi++) {
        int row = m0 + ((mi < 4) ? (tm * 4 + mi) : (64 + tm * 4 + mi - 4));
        float4 o;
        upk2(o.x, o.y, acc[mi][0]); upk2(o.z, o.w, acc[mi][1]);
        o.x += bi0.x; o.y += bi0.y; o.z += bi0.z; o.w += bi0.w;
        *(float4*)(C + (size_t)row * G4 + n0 + tn * 4) = o;
        upk2(o.x, o.y, acc[mi][2]); upk2(o.z, o.w, acc[mi][3]);
        o.x += bi1.x; o.y += bi1.y; o.z += bi1.z; o.w += bi1.w;
        *(float4*)(C + (size_t)row * G4 + n0 + 64 + tn * 4) = o;
    }
}

// ---------------- recurrent step: g = h_prev @ W_hh^T (+G), gate math, h/c update ----------------
// grid (16 j-tiles, 8 m-tiles) = 128 CTAs, 128 threads.
// Each CTA: 32 batch rows x 32 hidden cols x all 4 gates (N=128 of W_hh rows).
__global__ void __launch_bounds__(128) k_step(const float* __restrict__ Whh, int t, int layer) {
    const float* Gt = g_G + (size_t)t * BB * G4;
    const float* hp;
    float* hout;
    if (layer == 0) {
        hp   = t ? (g_h0s + (size_t)(t - 1) * BB * HH) : g_zero;
        hout = g_h0s + (size_t)t * BB * HH;
    } else {
        hp   = t ? (g_h1 + (size_t)((t - 1) & 1) * BB * HH) : g_zero;
        hout = g_h1 + (size_t)(t & 1) * BB * HH;
    }

    __shared__ float As[32][36];    // [k][m], 144B rows
    __shared__ float Bs[32][132];   // [k][n], n = gate*32 + jj

    int j0 = blockIdx.x * 32, m0 = blockIdx.y * 32;
    int tx = threadIdx.x;
    int tj = tx & 15, tm = tx >> 4;   // tm 0..7

    unsigned long long acc[4][4];     // [mi][gate], packed pair over 2 j's
#pragma unroll
    for (int i = 0; i < 4; i++)
#pragma unroll
        for (int g = 0; g < 4; g++) acc[i][g] = 0ull;

    for (int k0 = 0; k0 < HH; k0 += 32) {
#pragma unroll
        for (int i = 0; i < 2; i++) {
            int id = i * 128 + tx;
            int row = id >> 3;
            int kq = (id & 7) * 4;
            float4 v = *(const float4*)(hp + (size_t)(m0 + row) * HH + k0 + kq);
            As[kq + 0][row] = v.x; As[kq + 1][row] = v.y;
            As[kq + 2][row] = v.z; As[kq + 3][row] = v.w;
        }
#pragma unroll
        for (int i = 0; i < 8; i++) {
            int id = i * 128 + tx;
            int n = id >> 3;
            int kq = (id & 7) * 4;
            int wr = (n >> 5) * HH + j0 + (n & 31);   // gate*512 + j0 + jj
            float4 v = *(const float4*)(Whh + (size_t)wr * HH + k0 + kq);
            Bs[kq + 0][n] = v.x; Bs[kq + 1][n] = v.y;
            Bs[kq + 2][n] = v.z; Bs[kq + 3][n] = v.w;
        }
        __syncthreads();
#pragma unroll
        for (int k = 0; k < 32; k++) {
            float4 a = *(const float4*)&As[k][tm * 4];
            unsigned long long b0v = *(const unsigned long long*)&Bs[k][tj * 2];
            unsigned long long b1v = *(const unsigned long long*)&Bs[k][32 + tj * 2];
            unsigned long long b2v = *(const unsigned long long*)&Bs[k][64 + tj * 2];
            unsigned long long b3v = *(const unsigned long long*)&Bs[k][96 + tj * 2];
            float am[4] = { a.x, a.y, a.z, a.w };
#pragma unroll
            for (int mi = 0; mi < 4; mi++) {
                unsigned long long pa = pk2(am[mi], am[mi]);
                fma2(acc[mi][0], pa, b0v);
                fma2(acc[mi][1], pa, b1v);
                fma2(acc[mi][2], pa, b2v);
                fma2(acc[mi][3], pa, b3v);
            }
        }
        __syncthreads();
    }

    // epilogue: add input-GEMM gates, apply LSTM cell
#pragma unroll
    for (int mi = 0; mi < 4; mi++) {
        int m = m0 + tm * 4 + mi;
        const float* gr = Gt + (size_t)m * G4 + j0 + tj * 2;
        float2 gi = *(const float2*)(gr);
        float2 gf = *(const float2*)(gr + 512);
        float2 gg = *(const float2*)(gr + 1024);
        float2 go = *(const float2*)(gr + 1536);
        float i0, i1, f0, f1, gg0, gg1, o0, o1;
        upk2(i0, i1, acc[mi][0]);
        upk2(f0, f1, acc[mi][1]);
        upk2(gg0, gg1, acc[mi][2]);
        upk2(o0, o1, acc[mi][3]);
        i0 += gi.x; i1 += gi.y;
        f0 += gf.x; f1 += gf.y;
        gg0 += gg.x; gg1 += gg.y;
        o0 += go.x; o1 += go.y;

        int hix = m * HH + j0 + tj * 2;
        float2 cold = *(const float2*)&g_c[hix];
        float c0 = sigf(f0) * cold.x + sigf(i0) * tanhf(gg0);
        float c1 = sigf(f1) * cold.y + sigf(i1) * tanhf(gg1);
        float h0v = sigf(o0) * tanhf(c0);
        float h1v = sigf(o1) * tanhf(c1);
        *(float2*)&g_c[hix] = make_float2(c0, c1);
        *(float2*)(hout + hix) = make_float2(h0v, h1v);

        if (layer == 1) {
            if (t <= g_last[m]) {
                float2 pv = *(const float2*)&g_pooled[hix];
                pv.x = fmaxf(pv.x, h0v);
                pv.y = fmaxf(pv.y, h1v);
                *(float2*)&g_pooled[hix] = pv;
            }
        }
    }
}

// ---------------- final projection: logits = pooled @ W_out^T + b_out ----------------
__global__ void k_logits(const float* __restrict__ Wout, const float* __restrict__ bout,
                         float* __restrict__ out) {
    int b = blockIdx.x;
    int tx = threadIdx.x;
    float p[NCLS] = {0, 0, 0, 0, 0};
    for (int k = tx; k < HH; k += 128) {
        float v = g_pooled[b * HH + k];
#pragma unroll
        for (int c = 0; c < NCLS; c++) p[c] += v * Wout[c * HH + k];
    }
#pragma unroll
    for (int off = 16; off; off >>= 1)
#pragma unroll
        for (int c = 0; c < NCLS; c++) p[c] += __shfl_down_sync(0xffffffffu, p[c], off);
    __shared__ float red[4][NCLS];
    if ((tx & 31) == 0)
#pragma unroll
        for (int c = 0; c < NCLS; c++) red[tx >> 5][c] = p[c];
    __syncthreads();
    if (tx == 0) {
#pragma unroll
        for (int c = 0; c < NCLS; c++)
            out[b * NCLS + c] = red[0][c] + red[1][c] + red[2][c] + red[3][c] + bout[c];
    }
}

// ---------------- launch ----------------
extern "C" void kernel_launch(void* const* d_in, const int* in_sizes, int n_in,
                              void* d_out, int out_size) {
    (void)in_sizes; (void)n_in; (void)out_size;
    const int*   X      = (const int*)d_in[0];
    const float* emb    = (const float*)d_in[1];
    const float* W_ih0  = (const float*)d_in[2];
    const float* W_hh0  = (const float*)d_in[3];
    const float* b0     = (const float*)d_in[4];
    const float* W_ih1  = (const float*)d_in[5];
    const float* W_hh1  = (const float*)d_in[6];
    const float* b1     = (const float*)d_in[7];
    const float* W_out  = (const float*)d_in[8];
    const float* b_out  = (const float*)d_in[9];
    float* out = (float*)d_out;

    k_last<<<1, 256>>>(X);
    k_padw0<<<(G4 * EP + 255) / 256, 256>>>(W_ih0);
    k_gather<<<MROWS, 128>>>(X, emb);
    k_gemm<<<dim3(16, 400), 256>>>(nullptr, b0, 0);   // G0 = xe @ W0p^T + b0
    k_init<<<(BB * HH + 255) / 256, 256>>>(0);
    for (int t = 0; t < TT; t++)
        k_step<<<dim3(16, 8), 128>>>(W_hh0, t, 0);
    k_gemm<<<dim3(16, 400), 256>>>(W_ih1, b1, 1);     // G1 = h0s @ W_ih1^T + b1
    k_init<<<(BB * HH + 255) / 256, 256>>>(1);
    for (int t = 0; t < TT; t++)
        k_step<<<dim3(16, 8), 128>>>(W_hh1, t, 1);
    k_logits<<<BB, 128>>>(W_out, b_out, out);
}

// round 2
// speedup vs baseline: 1.3278x; 1.3278x over previous
#include <cuda_runtime.h>
#include <math.h>
#include <float.h>

#define BB 256
#define TT 200
#define EE 100
#define EP 112
#define HH 512
#define G4 2048
#define NCLS 5
#define VV 50000
#define MROWS (TT*BB)

// ---------------- static device scratch ----------------
__device__ float g_xe[(size_t)MROWS * EP];
__device__ float g_W0p[(size_t)G4 * EP];
__device__ float g_G[(size_t)MROWS * G4];
__device__ float g_h0s[(size_t)MROWS * HH];   // layer0 h archive (A for G1 GEMM)
__device__ float g_h1[2 * BB * HH];           // layer1 h double buffer
__device__ float g_pooled[BB * HH];
__device__ int   g_last[BB];
__device__ int   g_ctr;                        // global barrier counter

// ---------------- packed f32x2 helpers ----------------
__device__ __forceinline__ unsigned long long pk2(float lo, float hi) {
    unsigned long long r;
    asm("mov.b64 %0, {%1,%2};" : "=l"(r) : "f"(lo), "f"(hi));
    return r;
}
__device__ __forceinline__ void upk2(float& lo, float& hi, unsigned long long v) {
    asm("mov.b64 {%0,%1}, %2;" : "=f"(lo), "=f"(hi) : "l"(v));
}
__device__ __forceinline__ void fma2(unsigned long long& d, unsigned long long a, unsigned long long b) {
    asm("fma.rn.f32x2 %0, %1, %2, %0;" : "+l"(d) : "l"(a), "l"(b));
}
__device__ __forceinline__ int ldcg_i(const int* p) {
    int v; asm volatile("ld.global.cg.b32 %0, [%1];" : "=r"(v) : "l"(p)); return v;
}
__device__ __forceinline__ float sigf(float x)   { return 1.0f / (1.0f + __expf(-x)); }
__device__ __forceinline__ float tanhf_(float x) { return 2.0f / (1.0f + __expf(-2.0f * x)) - 1.0f; }

// ---------------- prep kernels ----------------
__global__ void k_last(const int* __restrict__ X) {
    int b = threadIdx.x;
    if (b < BB) {
        int l = -1;
        for (int t = 0; t < TT; t++)
            if (X[b * TT + t] != VV) l = t;
        g_last[b] = l;
    }
}

__global__ void k_zero() { if (threadIdx.x == 0) g_ctr = 0; }

__global__ void k_padw0(const float* __restrict__ W) {
    int idx = blockIdx.x * blockDim.x + threadIdx.x;
    if (idx < G4 * EP) {
        int n = idx / EP, k = idx % EP;
        g_W0p[idx] = (k < EE) ? W[n * EE + k] : 0.0f;
    }
}

__global__ void k_gather(const int* __restrict__ X, const float* __restrict__ emb) {
    int row = blockIdx.x;
    int t = row / BB, b = row % BB;
    int tok = X[b * TT + t];
    const float* src = emb + (size_t)tok * EE;
    for (int e = threadIdx.x; e < EP; e += blockDim.x)
        g_xe[(size_t)row * EP + e] = (e < EE) ? src[e] : 0.0f;
}

// ---------------- input GEMM: C[M,4H] = A[M,K] @ W[4H,K]^T + bias ----------------
// 128x128 tile, 256 threads, register-prefetch double buffering.
__global__ void __launch_bounds__(256) k_gemm(const float* __restrict__ Wihp,
                                              const float* __restrict__ bias,
                                              int which) {
    const float* A; const float* W; int K;
    if (which == 0) { A = g_xe;  W = g_W0p; K = EP; }
    else            { A = g_h0s; W = Wihp;  K = HH; }
    float* C = g_G;

    __shared__ float As[16][132];
    __shared__ float Bs[16][132];

    int m0 = blockIdx.y * 128, n0 = blockIdx.x * 128;
    int tx = threadIdx.x;
    int tn = tx & 15, tm = tx >> 4;

    unsigned long long acc[8][4];
#pragma unroll
    for (int i = 0; i < 8; i++)
#pragma unroll
        for (int j = 0; j < 4; j++) acc[i][j] = 0ull;

    int nt = K / 16;
    float4 va[2], vb[2];
#pragma unroll
    for (int i = 0; i < 2; i++) {
        int id = i * 256 + tx;
        int row = id >> 2, kq = (id & 3) * 4;
        va[i] = *(const float4*)(A + (size_t)(m0 + row) * K + kq);
        vb[i] = *(const float4*)(W + (size_t)(n0 + row) * K + kq);
    }

#pragma unroll 1
    for (int kt = 0; kt < nt; kt++) {
        float4 nva[2], nvb[2];
        if (kt + 1 < nt) {
            int k0n = (kt + 1) * 16;
#pragma unroll
            for (int i = 0; i < 2; i++) {
                int id = i * 256 + tx;
                int row = id >> 2, kq = (id & 3) * 4;
                nva[i] = *(const float4*)(A + (size_t)(m0 + row) * K + k0n + kq);
                nvb[i] = *(const float4*)(W + (size_t)(n0 + row) * K + k0n + kq);
            }
        }
#pragma unroll
        for (int i = 0; i < 2; i++) {
            int id = i * 256 + tx;
            int row = id >> 2, kq = (id & 3) * 4;
            As[kq + 0][row] = va[i].x; As[kq + 1][row] = va[i].y;
            As[kq + 2][row] = va[i].z; As[kq + 3][row] = va[i].w;
            Bs[kq + 0][row] = vb[i].x; Bs[kq + 1][row] = vb[i].y;
            Bs[kq + 2][row] = vb[i].z; Bs[kq + 3][row] = vb[i].w;
        }
        __syncthreads();
#pragma unroll
        for (int k = 0; k < 16; k++) {
            float4 a0 = *(const float4*)&As[k][tm * 4];
            float4 a1 = *(const float4*)&As[k][64 + tm * 4];
            unsigned long long pb[4];
            pb[0] = *(const unsigned long long*)&Bs[k][tn * 4];
            pb[1] = *(const unsigned long long*)&Bs[k][tn * 4 + 2];
            pb[2] = *(const unsigned long long*)&Bs[k][64 + tn * 4];
            pb[3] = *(const unsigned long long*)&Bs[k][64 + tn * 4 + 2];
            float am[8] = { a0.x, a0.y, a0.z, a0.w, a1.x, a1.y, a1.z, a1.w };
#pragma unroll
            for (int mi = 0; mi < 8; mi++) {
                unsigned long long pa = pk2(am[mi], am[mi]);
#pragma unroll
                for (int np = 0; np < 4; np++) fma2(acc[mi][np], pa, pb[np]);
            }
        }
        __syncthreads();
#pragma unroll
        for (int i = 0; i < 2; i++) { va[i] = nva[i]; vb[i] = nvb[i]; }
    }

    float4 bi0 = *(const float4*)(bias + n0 + tn * 4);
    float4 bi1 = *(const float4*)(bias + n0 + 64 + tn * 4);
#pragma unroll
    for (int mi = 0; mi < 8; mi++) {
        int row = m0 + ((mi < 4) ? (tm * 4 + mi) : (64 + tm * 4 + mi - 4));
        float4 o;
        upk2(o.x, o.y, acc[mi][0]); upk2(o.z, o.w, acc[mi][1]);
        o.x += bi0.x; o.y += bi0.y; o.z += bi0.z; o.w += bi0.w;
        *(float4*)(C + (size_t)row * G4 + n0 + tn * 4) = o;
        upk2(o.x, o.y, acc[mi][2]); upk2(o.z, o.w, acc[mi][3]);
        o.x += bi1.x; o.y += bi1.y; o.z += bi1.z; o.w += bi1.w;
        *(float4*)(C + (size_t)row * G4 + n0 + 64 + tn * 4) = o;
    }
}

// ---------------- persistent recurrence kernel ----------------
// grid (32 j-tiles, 4 m-tiles) = 128 CTAs, 256 threads, all co-resident.
// CTA tile: 64 m x (4 gates x 16 j) x 512 k.  W slab resident in SMEM (128 KB).
// Per thread: 2 m x 2 j x 4 gates; c/pool/G in registers.
#define RS_WS   (HH * 64)          // 512*64 floats = 128 KB
#define RS_AS   (32 * 130)         // dup A staging (+2 pad)
#define RS_SMEM ((RS_WS + RS_AS) * 4)

template<int LAYER>
__global__ void __launch_bounds__(256) k_recur(const float* __restrict__ Whh) {
    extern __shared__ float sm[];
    float* Ws  = sm;               // [512][64]  (k-major)
    float* As2 = sm + RS_WS;       // [32][130]  duplicated pairs

    int j0 = blockIdx.x * 16;
    int m0 = blockIdx.y * 64;
    int tx = threadIdx.x;
    int tj = tx & 7, tm = tx >> 3;         // tj 0..7, tm 0..31

    // ---- stage W slab once: Ws[k][g*16+jj] = Whh[(g*512 + j0+jj)*512 + k] ----
    {
        int n = tx >> 2;                   // 0..63
        int g = n >> 4, jj = n & 15;
        int kb = (tx & 3) * 128;
        const float* wr = Whh + (size_t)(g * 512 + j0 + jj) * HH + kb;
#pragma unroll 4
        for (int k = 0; k < 128; k += 4) {
            float4 v = *(const float4*)(wr + k);
            int kk = kb + k;
            Ws[(kk + 0) * 64 + n] = v.x;
            Ws[(kk + 1) * 64 + n] = v.y;
            Ws[(kk + 2) * 64 + n] = v.z;
            Ws[(kk + 3) * 64 + n] = v.w;
        }
    }
    __syncthreads();

    // persistent per-thread state
    float2 cst[2] = { {0.f, 0.f}, {0.f, 0.f} };
    float2 pool[2];
    int lastv[2];
    if (LAYER == 1) {
        pool[0] = make_float2(-FLT_MAX, -FLT_MAX);
        pool[1] = make_float2(-FLT_MAX, -FLT_MAX);
        lastv[0] = g_last[m0 + 2 * tm];
        lastv[1] = g_last[m0 + 2 * tm + 1];
    }

    // staging ids
    int r0 = tx >> 3, q0 = (tx & 7) * 4;           // ids 0..255
    int r1 = 32 + (tx >> 3), q1 = q0;              // ids 256..511

    for (int t = 0; t < TT; t++) {
        const float* Gt = g_G + (size_t)t * BB * G4;

        // prefetch gate inputs (DRAM) — consumed after k-loop
        float2 gv[2][4];
#pragma unroll
        for (int mi = 0; mi < 2; mi++) {
            int m = m0 + 2 * tm + mi;
            const float* gr = Gt + (size_t)m * G4 + j0 + 2 * tj;
#pragma unroll
            for (int g = 0; g < 4; g++) gv[mi][g] = *(const float2*)(gr + g * 512);
        }

        unsigned long long acc[2][4];
#pragma unroll
        for (int mi = 0; mi < 2; mi++)
#pragma unroll
            for (int g = 0; g < 4; g++) acc[mi][g] = 0ull;

        if (t > 0) {
            const float* hp = (LAYER == 0)
                ? g_h0s + (size_t)(t - 1) * BB * HH
                : g_h1 + (size_t)((t - 1) & 1) * BB * HH;
            float4 pA = __ldcg((const float4*)(hp + (size_t)(m0 + r0) * HH + q0));
            float4 pB = __ldcg((const float4*)(hp + (size_t)(m0 + r1) * HH + q1));
#pragma unroll 1
            for (int kt = 0; kt < 16; kt++) {
                float4 nA, nB;
                if (kt + 1 < 16) {
                    int k0n = (kt + 1) * 32;
                    nA = __ldcg((const float4*)(hp + (size_t)(m0 + r0) * HH + k0n + q0));
                    nB = __ldcg((const float4*)(hp + (size_t)(m0 + r1) * HH + k0n + q1));
                }
                // store duplicated pairs
                *(unsigned long long*)&As2[(q0 + 0) * 130 + 2 * r0] = pk2(pA.x, pA.x);
                *(unsigned long long*)&As2[(q0 + 1) * 130 + 2 * r0] = pk2(pA.y, pA.y);
                *(unsigned long long*)&As2[(q0 + 2) * 130 + 2 * r0] = pk2(pA.z, pA.z);
                *(unsigned long long*)&As2[(q0 + 3) * 130 + 2 * r0] = pk2(pA.w, pA.w);
                *(unsigned long long*)&As2[(q1 + 0) * 130 + 2 * r1] = pk2(pB.x, pB.x);
                *(unsigned long long*)&As2[(q1 + 1) * 130 + 2 * r1] = pk2(pB.y, pB.y);
                *(unsigned long long*)&As2[(q1 + 2) * 130 + 2 * r1] = pk2(pB.z, pB.z);
                *(unsigned long long*)&As2[(q1 + 3) * 130 + 2 * r1] = pk2(pB.w, pB.w);
                __syncthreads();
                const float* WsK = Ws + kt * 32 * 64;
#pragma unroll
                for (int k = 0; k < 32; k++) {
                    unsigned long long a0 = *(const unsigned long long*)&As2[k * 130 + 4 * tm];
                    unsigned long long a1 = *(const unsigned long long*)&As2[k * 130 + 4 * tm + 2];
                    const float* wrow = WsK + k * 64 + tj * 2;
                    unsigned long long b0 = *(const unsigned long long*)(wrow);
                    unsigned long long b1 = *(const unsigned long long*)(wrow + 16);
                    unsigned long long b2 = *(const unsigned long long*)(wrow + 32);
                    unsigned long long b3 = *(const unsigned long long*)(wrow + 48);
                    fma2(acc[0][0], a0, b0); fma2(acc[0][1], a0, b1);
                    fma2(acc[0][2], a0, b2); fma2(acc[0][3], a0, b3);
                    fma2(acc[1][0], a1, b0); fma2(acc[1][1], a1, b1);
                    fma2(acc[1][2], a1, b2); fma2(acc[1][3], a1, b3);
                }
                __syncthreads();
                pA = nA; pB = nB;
            }
        }

        // epilogue: gates -> c,h ; write h ; pool
        float* hout = (LAYER == 0)
            ? g_h0s + (size_t)t * BB * HH
            : g_h1 + (size_t)(t & 1) * BB * HH;
#pragma unroll
        for (int mi = 0; mi < 2; mi++) {
            float i0, i1, f0, f1, gg0, gg1, o0, o1;
            upk2(i0, i1, acc[mi][0]);
            upk2(f0, f1, acc[mi][1]);
            upk2(gg0, gg1, acc[mi][2]);
            upk2(o0, o1, acc[mi][3]);
            i0 += gv[mi][0].x; i1 += gv[mi][0].y;
            f0 += gv[mi][1].x; f1 += gv[mi][1].y;
            gg0 += gv[mi][2].x; gg1 += gv[mi][2].y;
            o0 += gv[mi][3].x; o1 += gv[mi][3].y;

            float c0 = sigf(f0) * cst[mi].x + sigf(i0) * tanhf_(gg0);
            float c1 = sigf(f1) * cst[mi].y + sigf(i1) * tanhf_(gg1);
            cst[mi].x = c0; cst[mi].y = c1;
            float h0v = sigf(o0) * tanhf_(c0);
            float h1v = sigf(o1) * tanhf_(c1);

            int m = m0 + 2 * tm + mi;
            *(float2*)(hout + (size_t)m * HH + j0 + 2 * tj) = make_float2(h0v, h1v);

            if (LAYER == 1 && t <= lastv[mi]) {
                pool[mi].x = fmaxf(pool[mi].x, h0v);
                pool[mi].y = fmaxf(pool[mi].y, h1v);
            }
        }

        // global barrier between steps (skip after last)
        if (t != TT - 1) {
            __threadfence();
            __syncthreads();
            if (tx == 0) {
                atomicAdd(&g_ctr, 1);
                int target = 128 * (t + 1);
                while (ldcg_i(&g_ctr) < target) __nanosleep(40);
            }
            __syncthreads();
        }
    }

    if (LAYER == 1) {
#pragma unroll
        for (int mi = 0; mi < 2; mi++) {
            int m = m0 + 2 * tm + mi;
            *(float2*)&g_pooled[m * HH + j0 + 2 * tj] = pool[mi];
        }
    }
}

// ---------------- final projection ----------------
__global__ void k_logits(const float* __restrict__ Wout, const float* __restrict__ bout,
                         float* __restrict__ out) {
    int b = blockIdx.x;
    int tx = threadIdx.x;
    float p[NCLS] = {0, 0, 0, 0, 0};
    for (int k = tx; k < HH; k += 128) {
        float v = g_pooled[b * HH + k];
#pragma unroll
        for (int c = 0; c < NCLS; c++) p[c] += v * Wout[c * HH + k];
    }
#pragma unroll
    for (int off = 16; off; off >>= 1)
#pragma unroll
        for (int c = 0; c < NCLS; c++) p[c] += __shfl_down_sync(0xffffffffu, p[c], off);
    __shared__ float red[4][NCLS];
    if ((tx & 31) == 0)
#pragma unroll
        for (int c = 0; c < NCLS; c++) red[tx >> 5][c] = p[c];
    __syncthreads();
    if (tx == 0) {
#pragma unroll
        for (int c = 0; c < NCLS; c++)
            out[b * NCLS + c] = red[0][c] + red[1][c] + red[2][c] + red[3][c] + bout[c];
    }
}

// ---------------- launch ----------------
extern "C" void kernel_launch(void* const* d_in, const int* in_sizes, int n_in,
                              void* d_out, int out_size) {
    (void)in_sizes; (void)n_in; (void)out_size;
    const int*   X      = (const int*)d_in[0];
    const float* emb    = (const float*)d_in[1];
    const float* W_ih0  = (const float*)d_in[2];
    const float* W_hh0  = (const float*)d_in[3];
    const float* b0     = (const float*)d_in[4];
    const float* W_ih1  = (const float*)d_in[5];
    const float* W_hh1  = (const float*)d_in[6];
    const float* b1     = (const float*)d_in[7];
    const float* W_out  = (const float*)d_in[8];
    const float* b_out  = (const float*)d_in[9];
    float* out = (float*)d_out;

    cudaFuncSetAttribute(k_recur<0>, cudaFuncAttributeMaxDynamicSharedMemorySize, RS_SMEM);
    cudaFuncSetAttribute(k_recur<1>, cudaFuncAttributeMaxDynamicSharedMemorySize, RS_SMEM);

    k_last<<<1, 256>>>(X);
    k_padw0<<<(G4 * EP + 255) / 256, 256>>>(W_ih0);
    k_gather<<<MROWS, 128>>>(X, emb);
    k_gemm<<<dim3(16, 400), 256>>>(nullptr, b0, 0);
    k_zero<<<1, 1>>>();
    k_recur<0><<<dim3(32, 4), 256, RS_SMEM>>>(W_hh0);
    k_gemm<<<dim3(16, 400), 256>>>(W_ih1, b1, 1);
    k_zero<<<1, 1>>>();
    k_recur<1><<<dim3(32, 4), 256, RS_SMEM>>>(W_hh1);
    k_logits<<<BB, 128>>>(W_out, b_out, out);
}

// round 3
// speedup vs baseline: 1.6199x; 1.2201x over previous
#include <cuda_runtime.h>
#include <math.h>
#include <float.h>

#define BB 256
#define TT 200
#define EE 100
#define EP 112
#define HH 512
#define G4 2048
#define NCLS 5
#define VV 50000
#define MROWS (TT*BB)

// ---------------- static device scratch ----------------
__device__ float g_xe[(size_t)MROWS * EP];
__device__ float g_W0p[(size_t)G4 * EP];
__device__ float g_G[(size_t)MROWS * G4];
__device__ float g_h0s[(size_t)MROWS * HH];   // layer0 h archive (A for G1 GEMM)
__device__ float g_h1[2 * BB * HH];           // layer1 h double buffer
__device__ float g_pooled[BB * HH];
__device__ int   g_last[BB];
__device__ unsigned g_A;                       // monotonic arrivals (never reset)
__device__ unsigned g_R;                       // monotonic releases  (never reset)

// ---------------- packed f32x2 helpers ----------------
__device__ __forceinline__ unsigned long long pk2(float lo, float hi) {
    unsigned long long r;
    asm("mov.b64 %0, {%1,%2};" : "=l"(r) : "f"(lo), "f"(hi));
    return r;
}
__device__ __forceinline__ void upk2(float& lo, float& hi, unsigned long long v) {
    asm("mov.b64 {%0,%1}, %2;" : "=f"(lo), "=f"(hi) : "l"(v));
}
__device__ __forceinline__ void fma2(unsigned long long& d, unsigned long long a, unsigned long long b) {
    asm("fma.rn.f32x2 %0, %1, %2, %0;" : "+l"(d) : "l"(a), "l"(b));
}
__device__ __forceinline__ unsigned ldcg_u(const unsigned* p) {
    unsigned v; asm volatile("ld.global.cg.b32 %0, [%1];" : "=r"(v) : "l"(p)); return v;
}
__device__ __forceinline__ float sigf(float x)   { return 1.0f / (1.0f + __expf(-x)); }
__device__ __forceinline__ float tanhf_(float x) { return 2.0f / (1.0f + __expf(-2.0f * x)) - 1.0f; }

// ---------------- prep kernels ----------------
__global__ void k_last(const int* __restrict__ X) {
    int b = threadIdx.x;
    if (b < BB) {
        int l = -1;
        for (int t = 0; t < TT; t++)
            if (X[b * TT + t] != VV) l = t;
        g_last[b] = l;
    }
}

__global__ void k_padw0(const float* __restrict__ W) {
    int idx = blockIdx.x * blockDim.x + threadIdx.x;
    if (idx < G4 * EP) {
        int n = idx / EP, k = idx % EP;
        g_W0p[idx] = (k < EE) ? W[n * EE + k] : 0.0f;
    }
}

__global__ void k_gather(const int* __restrict__ X, const float* __restrict__ emb) {
    int row = blockIdx.x;
    int t = row / BB, b = row % BB;
    int tok = X[b * TT + t];
    const float* src = emb + (size_t)tok * EE;
    for (int e = threadIdx.x; e < EP; e += blockDim.x)
        g_xe[(size_t)row * EP + e] = (e < EE) ? src[e] : 0.0f;
}

// ---------------- input GEMM: C[M,4H] = A[M,K] @ W[4H,K]^T + bias ----------------
__global__ void __launch_bounds__(256) k_gemm(const float* __restrict__ Wihp,
                                              const float* __restrict__ bias,
                                              int which) {
    const float* A; const float* W; int K;
    if (which == 0) { A = g_xe;  W = g_W0p; K = EP; }
    else            { A = g_h0s; W = Wihp;  K = HH; }
    float* C = g_G;

    __shared__ float As[16][132];
    __shared__ float Bs[16][132];

    int m0 = blockIdx.y * 128, n0 = blockIdx.x * 128;
    int tx = threadIdx.x;
    int tn = tx & 15, tm = tx >> 4;

    unsigned long long acc[8][4];
#pragma unroll
    for (int i = 0; i < 8; i++)
#pragma unroll
        for (int j = 0; j < 4; j++) acc[i][j] = 0ull;

    int nt = K / 16;
    float4 va[2], vb[2];
#pragma unroll
    for (int i = 0; i < 2; i++) {
        int id = i * 256 + tx;
        int row = id >> 2, kq = (id & 3) * 4;
        va[i] = *(const float4*)(A + (size_t)(m0 + row) * K + kq);
        vb[i] = *(const float4*)(W + (size_t)(n0 + row) * K + kq);
    }

#pragma unroll 1
    for (int kt = 0; kt < nt; kt++) {
        float4 nva[2], nvb[2];
        if (kt + 1 < nt) {
            int k0n = (kt + 1) * 16;
#pragma unroll
            for (int i = 0; i < 2; i++) {
                int id = i * 256 + tx;
                int row = id >> 2, kq = (id & 3) * 4;
                nva[i] = *(const float4*)(A + (size_t)(m0 + row) * K + k0n + kq);
                nvb[i] = *(const float4*)(W + (size_t)(n0 + row) * K + k0n + kq);
            }
        }
#pragma unroll
        for (int i = 0; i < 2; i++) {
            int id = i * 256 + tx;
            int row = id >> 2, kq = (id & 3) * 4;
            As[kq + 0][row] = va[i].x; As[kq + 1][row] = va[i].y;
            As[kq + 2][row] = va[i].z; As[kq + 3][row] = va[i].w;
            Bs[kq + 0][row] = vb[i].x; Bs[kq + 1][row] = vb[i].y;
            Bs[kq + 2][row] = vb[i].z; Bs[kq + 3][row] = vb[i].w;
        }
        __syncthreads();
#pragma unroll
        for (int k = 0; k < 16; k++) {
            float4 a0 = *(const float4*)&As[k][tm * 4];
            float4 a1 = *(const float4*)&As[k][64 + tm * 4];
            unsigned long long pb[4];
            pb[0] = *(const unsigned long long*)&Bs[k][tn * 4];
            pb[1] = *(const unsigned long long*)&Bs[k][tn * 4 + 2];
            pb[2] = *(const unsigned long long*)&Bs[k][64 + tn * 4];
            pb[3] = *(const unsigned long long*)&Bs[k][64 + tn * 4 + 2];
            float am[8] = { a0.x, a0.y, a0.z, a0.w, a1.x, a1.y, a1.z, a1.w };
#pragma unroll
            for (int mi = 0; mi < 8; mi++) {
                unsigned long long pa = pk2(am[mi], am[mi]);
#pragma unroll
                for (int np = 0; np < 4; np++) fma2(acc[mi][np], pa, pb[np]);
            }
        }
        __syncthreads();
#pragma unroll
        for (int i = 0; i < 2; i++) { va[i] = nva[i]; vb[i] = nvb[i]; }
    }

    float4 bi0 = *(const float4*)(bias + n0 + tn * 4);
    float4 bi1 = *(const float4*)(bias + n0 + 64 + tn * 4);
#pragma unroll
    for (int mi = 0; mi < 8; mi++) {
        int row = m0 + ((mi < 4) ? (tm * 4 + mi) : (64 + tm * 4 + mi - 4));
        float4 o;
        upk2(o.x, o.y, acc[mi][0]); upk2(o.z, o.w, acc[mi][1]);
        o.x += bi0.x; o.y += bi0.y; o.z += bi0.z; o.w += bi0.w;
        *(float4*)(C + (size_t)row * G4 + n0 + tn * 4) = o;
        upk2(o.x, o.y, acc[mi][2]); upk2(o.z, o.w, acc[mi][3]);
        o.x += bi1.x; o.y += bi1.y; o.z += bi1.z; o.w += bi1.w;
        *(float4*)(C + (size_t)row * G4 + n0 + 64 + tn * 4) = o;
    }
}

// ---------------- persistent recurrence kernel ----------------
// grid (32 j-tiles, 4 m-tiles) = 128 CTAs, 256 threads.
// CTA tile: 64m x (4g x 16j) x 512k.  W slab resident in SMEM.
// Ws layout: row k (stride 68 floats). cols 0..31  = [tj][g0 pair, g1 pair]
//            cols 32..63 = [tj][g2 pair, g3 pair]  -> 2 conflict-free LDS.128/thread/k.
#define WS_STRIDE 68
#define RS_WS   (HH * WS_STRIDE)                // 34816 floats
#define RS_AS   (2 * 32 * 130)                  // double-buffered dup-A staging
#define RS_SMEM ((RS_WS + RS_AS) * 4)

template<int LAYER>
__global__ void __launch_bounds__(256) k_recur(const float* __restrict__ Whh) {
    extern __shared__ float sm[];
    float* Ws  = sm;                 // [512][68]
    float* As2 = sm + RS_WS;         // [2][32][130]

    int j0 = blockIdx.x * 16;
    int m0 = blockIdx.y * 64;
    int tx = threadIdx.x;
    int tj = tx & 7, tm = tx >> 3;   // tj 0..7, tm 0..31

    unsigned r0snap = ldcg_u(&g_R);  // stable: first release needs all CTAs arrived

    // ---- stage W slab once ----
    // col c (0..63): blk=c>>5, tjj=(c>>2)&7, rem=c&3, g=2*blk+(rem>>1), j=j0+2*tjj+(rem&1)
    {
        int c = tx >> 2;
        int blk = c >> 5, tjj = (c >> 2) & 7, rem = c & 3;
        int g = 2 * blk + (rem >> 1);
        int jj = j0 + 2 * tjj + (rem & 1);
        int kb = (tx & 3) * 128;
        const float* wr = Whh + (size_t)(g * HH + jj) * HH + kb;
#pragma unroll 4
        for (int k = 0; k < 128; k += 4) {
            float4 v = *(const float4*)(wr + k);
            int kk = kb + k;
            Ws[(kk + 0) * WS_STRIDE + c] = v.x;
            Ws[(kk + 1) * WS_STRIDE + c] = v.y;
            Ws[(kk + 2) * WS_STRIDE + c] = v.z;
            Ws[(kk + 3) * WS_STRIDE + c] = v.w;
        }
    }
    __syncthreads();

    float2 cst[2] = { {0.f, 0.f}, {0.f, 0.f} };
    float2 pool[2];
    int lastv[2];
    if (LAYER == 1) {
        pool[0] = make_float2(-FLT_MAX, -FLT_MAX);
        pool[1] = make_float2(-FLT_MAX, -FLT_MAX);
        lastv[0] = g_last[m0 + 2 * tm];
        lastv[1] = g_last[m0 + 2 * tm + 1];
    }

    // staging ids
    int sr0 = tx >> 3, sq0 = (tx & 7) * 4;
    int sr1 = 32 + (tx >> 3);

    // prefetch gate inputs for t=0
    float2 gv[2][4];
    {
        const float* Gt = g_G;
#pragma unroll
        for (int mi = 0; mi < 2; mi++) {
            const float* gr = Gt + (size_t)(m0 + 2 * tm + mi) * G4 + j0 + 2 * tj;
#pragma unroll
            for (int g = 0; g < 4; g++) gv[mi][g] = __ldcg((const float2*)(gr + g * 512));
        }
    }

    for (int t = 0; t < TT; t++) {
        unsigned long long acc[2][4];
#pragma unroll
        for (int mi = 0; mi < 2; mi++)
#pragma unroll
            for (int g = 0; g < 4; g++) acc[mi][g] = 0ull;

        if (t > 0) {
            const float* hp = (LAYER == 0)
                ? g_h0s + (size_t)(t - 1) * BB * HH
                : g_h1 + (size_t)((t - 1) & 1) * BB * HH;
            float4 pA = __ldcg((const float4*)(hp + (size_t)(m0 + sr0) * HH + sq0));
            float4 pB = __ldcg((const float4*)(hp + (size_t)(m0 + sr1) * HH + sq0));
#pragma unroll 1
            for (int kt = 0; kt < 16; kt++) {
                float4 nA, nB;
                if (kt + 1 < 16) {
                    int k0n = (kt + 1) * 32;
                    nA = __ldcg((const float4*)(hp + (size_t)(m0 + sr0) * HH + k0n + sq0));
                    nB = __ldcg((const float4*)(hp + (size_t)(m0 + sr1) * HH + k0n + sq0));
                }
                float* Ab = As2 + (kt & 1) * (32 * 130);
                *(unsigned long long*)&Ab[(sq0 + 0) * 130 + 2 * sr0] = pk2(pA.x, pA.x);
                *(unsigned long long*)&Ab[(sq0 + 1) * 130 + 2 * sr0] = pk2(pA.y, pA.y);
                *(unsigned long long*)&Ab[(sq0 + 2) * 130 + 2 * sr0] = pk2(pA.z, pA.z);
                *(unsigned long long*)&Ab[(sq0 + 3) * 130 + 2 * sr0] = pk2(pA.w, pA.w);
                *(unsigned long long*)&Ab[(sq0 + 0) * 130 + 2 * sr1] = pk2(pB.x, pB.x);
                *(unsigned long long*)&Ab[(sq0 + 1) * 130 + 2 * sr1] = pk2(pB.y, pB.y);
                *(unsigned long long*)&Ab[(sq0 + 2) * 130 + 2 * sr1] = pk2(pB.z, pB.z);
                *(unsigned long long*)&Ab[(sq0 + 3) * 130 + 2 * sr1] = pk2(pB.w, pB.w);
                __syncthreads();
                const float* WsK = Ws + (size_t)kt * 32 * WS_STRIDE;
#pragma unroll
                for (int k = 0; k < 32; k++) {
                    unsigned long long a0 = *(const unsigned long long*)&Ab[k * 130 + 4 * tm];
                    unsigned long long a1 = *(const unsigned long long*)&Ab[k * 130 + 4 * tm + 2];
                    ulonglong2 b01 = *(const ulonglong2*)&WsK[k * WS_STRIDE + tj * 4];
                    ulonglong2 b23 = *(const ulonglong2*)&WsK[k * WS_STRIDE + 32 + tj * 4];
                    fma2(acc[0][0], a0, b01.x); fma2(acc[0][1], a0, b01.y);
                    fma2(acc[0][2], a0, b23.x); fma2(acc[0][3], a0, b23.y);
                    fma2(acc[1][0], a1, b01.x); fma2(acc[1][1], a1, b01.y);
                    fma2(acc[1][2], a1, b23.x); fma2(acc[1][3], a1, b23.y);
                }
                pA = nA; pB = nB;
            }
        }

        // ---- epilogue ----
        float* hout = (LAYER == 0)
            ? g_h0s + (size_t)t * BB * HH
            : g_h1 + (size_t)(t & 1) * BB * HH;
#pragma unroll
        for (int mi = 0; mi < 2; mi++) {
            float i0, i1, f0, f1, gg0, gg1, o0, o1;
            upk2(i0, i1, acc[mi][0]);
            upk2(f0, f1, acc[mi][1]);
            upk2(gg0, gg1, acc[mi][2]);
            upk2(o0, o1, acc[mi][3]);
            i0 += gv[mi][0].x; i1 += gv[mi][0].y;
            f0 += gv[mi][1].x; f1 += gv[mi][1].y;
            gg0 += gv[mi][2].x; gg1 += gv[mi][2].y;
            o0 += gv[mi][3].x; o1 += gv[mi][3].y;

            float c0 = sigf(f0) * cst[mi].x + sigf(i0) * tanhf_(gg0);
            float c1 = sigf(f1) * cst[mi].y + sigf(i1) * tanhf_(gg1);
            cst[mi].x = c0; cst[mi].y = c1;
            float h0v = sigf(o0) * tanhf_(c0);
            float h1v = sigf(o1) * tanhf_(c1);

            int m = m0 + 2 * tm + mi;
            __stcg((float2*)(hout + (size_t)m * HH + j0 + 2 * tj), make_float2(h0v, h1v));

            if (LAYER == 1 && t <= lastv[mi]) {
                pool[mi].x = fmaxf(pool[mi].x, h0v);
                pool[mi].y = fmaxf(pool[mi].y, h1v);
            }
        }

        // ---- inter-step barrier (monotonic counters, replay-safe) ----
        if (t != TT - 1) {
            __threadfence();
            __syncthreads();
            if (tx == 0) {
                unsigned old = atomicAdd(&g_A, 1u);
                if ((old & 127u) == 127u) atomicAdd(&g_R, 1u);
            }
            // overlap: prefetch next step's gates while waiting
            {
                const float* Gt = g_G + (size_t)(t + 1) * BB * G4;
#pragma unroll
                for (int mi = 0; mi < 2; mi++) {
                    const float* gr = Gt + (size_t)(m0 + 2 * tm + mi) * G4 + j0 + 2 * tj;
#pragma unroll
                    for (int g = 0; g < 4; g++) gv[mi][g] = __ldcg((const float2*)(gr + g * 512));
                }
            }
            if (tx == 0) {
                unsigned target = r0snap + (unsigned)(t + 1);
                while ((int)(ldcg_u(&g_R) - target) < 0) __nanosleep(32);
            }
            __syncthreads();
        }
    }

    if (LAYER == 1) {
#pragma unroll
        for (int mi = 0; mi < 2; mi++) {
            int m = m0 + 2 * tm + mi;
            *(float2*)&g_pooled[m * HH + j0 + 2 * tj] = pool[mi];
        }
    }
}

// ---------------- final projection ----------------
__global__ void k_logits(const float* __restrict__ Wout, const float* __restrict__ bout,
                         float* __restrict__ out) {
    int b = blockIdx.x;
    int tx = threadIdx.x;
    float p[NCLS] = {0, 0, 0, 0, 0};
    for (int k = tx; k < HH; k += 128) {
        float v = g_pooled[b * HH + k];
#pragma unroll
        for (int c = 0; c < NCLS; c++) p[c] += v * Wout[c * HH + k];
    }
#pragma unroll
    for (int off = 16; off; off >>= 1)
#pragma unroll
        for (int c = 0; c < NCLS; c++) p[c] += __shfl_down_sync(0xffffffffu, p[c], off);
    __shared__ float red[4][NCLS];
    if ((tx & 31) == 0)
#pragma unroll
        for (int c = 0; c < NCLS; c++) red[tx >> 5][c] = p[c];
    __syncthreads();
    if (tx == 0) {
#pragma unroll
        for (int c = 0; c < NCLS; c++)
            out[b * NCLS + c] = red[0][c] + red[1][c] + red[2][c] + red[3][c] + bout[c];
    }
}

// ---------------- launch ----------------
extern "C" void kernel_launch(void* const* d_in, const int* in_sizes, int n_in,
                              void* d_out, int out_size) {
    (void)in_sizes; (void)n_in; (void)out_size;
    const int*   X      = (const int*)d_in[0];
    const float* emb    = (const float*)d_in[1];
    const float* W_ih0  = (const float*)d_in[2];
    const float* W_hh0  = (const float*)d_in[3];
    const float* b0     = (const float*)d_in[4];
    const float* W_ih1  = (const float*)d_in[5];
    const float* W_hh1  = (const float*)d_in[6];
    const float* b1     = (const float*)d_in[7];
    const float* W_out  = (const float*)d_in[8];
    const float* b_out  = (const float*)d_in[9];
    float* out = (float*)d_out;

    cudaFuncSetAttribute(k_recur<0>, cudaFuncAttributeMaxDynamicSharedMemorySize, RS_SMEM);
    cudaFuncSetAttribute(k_recur<1>, cudaFuncAttributeMaxDynamicSharedMemorySize, RS_SMEM);

    // order chosen so the ncu capture slot lands on k_recur<0>
    k_padw0<<<(G4 * EP + 255) / 256, 256>>>(W_ih0);          // 1
    k_gather<<<MROWS, 128>>>(X, emb);                        // 2
    k_gemm<<<dim3(16, 400), 256>>>(nullptr, b0, 0);          // 3
    k_recur<0><<<dim3(32, 4), 256, RS_SMEM>>>(W_hh0);        // 4  <- capture target
    k_last<<<1, 256>>>(X);                                   // 5
    k_gemm<<<dim3(16, 400), 256>>>(W_ih1, b1, 1);            // 6
    k_recur<1><<<dim3(32, 4), 256, RS_SMEM>>>(W_hh1);        // 7
    k_logits<<<BB, 128>>>(W_out, b_out, out);                // 8
}